// round 9
// baseline (speedup 1.0000x reference)
#include <cuda_runtime.h>

#define Bn 64
#define Mn 200
#define Sn 50
#define Qn 20
#define Dn 128
#define Vn 50000
#define HOPSn 3
#define NEG_INF -1e9f

typedef unsigned long long ull;

// ---- packed fp32x2 helpers (sm_103a via PTX) ----
__device__ __forceinline__ ull pack2(float lo, float hi) {
    ull r; asm("mov.b64 %0, {%1, %2};" : "=l"(r) : "f"(lo), "f"(hi)); return r;
}
__device__ __forceinline__ float2 unpack2(ull v) {
    float2 f; asm("mov.b64 {%0, %1}, %2;" : "=f"(f.x), "=f"(f.y) : "l"(v)); return f;
}
__device__ __forceinline__ ull fma2(ull a, ull b, ull c) {
    ull d; asm("fma.rn.f32x2 %0, %1, %2, %3;" : "=l"(d) : "l"(a), "l"(b), "l"(c)); return d;
}
__device__ __forceinline__ ull add2(ull a, ull b) {
    ull d; asm("add.rn.f32x2 %0, %1, %2;" : "=l"(d) : "l"(a), "l"(b)); return d;
}
__device__ __forceinline__ ull sub2(ull a, ull b) {   // a - b
    ull d; asm("sub.rn.f32x2 %0, %1, %2;" : "=l"(d) : "l"(a), "l"(b)); return d;
}
__device__ __forceinline__ ull mul2(ull a, ull b) {
    ull d; asm("mul.rn.f32x2 %0, %1, %2;" : "=l"(d) : "l"(a), "l"(b)); return d;
}

// Scratch (static __device__ globals: allowed; no runtime allocation)
__device__ float g_emb[4][Bn * Mn][Dn];   // embeddings of A0, C0, C1, C2  (~26 MB)
__device__ float g_u[Bn][Dn];             // controller state after hops
__device__ int   g_nonpad[Bn * Mn];       // mem_nonpad mask

// ---------------------------------------------------------------------------
// Kernel 1: story embedding gather, MOMENT-FORM version.
//  PE weights are affine in s:  a=1-s'/50, b=2s'/50-1, so
//    emb_d = P_d*(1-c_d) + S1_d*(2c_d-1)/50,  P=Σ r_s, S1=Σ s'·r_s.
//  S1 via multiply-free prefix trick (rows in ascending s):
//    T += r ; Qn -= T   =>   S1_warp = (end+1)*T + Qn  (+ per-warp fixup).
//  Inner loop per row: LDS idx + IMAD + LDG.128 + 4 packed FADD2 (~7 instrs,
//  was ~13).  grid=(Bn*Mn, 4): y=table (L2 phase locality, proven R4).
// ---------------------------------------------------------------------------
__global__ void __launch_bounds__(128) embed_story_kernel(
    const int* __restrict__ story,
    const float* __restrict__ T0, const float* __restrict__ T1,
    const float* __restrict__ T2, const float* __restrict__ T3)
{
    __shared__ int    idx[Sn];
    __shared__ float4 part[4][32];
    const int bm   = blockIdx.x;
    const int tb   = blockIdx.y;
    const int t    = threadIdx.x;
    const int warp = t >> 5;
    const int lane = t & 31;

    if (t < Sn) idx[t] = story[bm * Sn + t];
    __syncthreads();
    if (tb == 0) {
        int np = __syncthreads_or((t < Sn) && (idx[t] != 0));
        if (t == 0) g_nonpad[bm] = np;
    }

    const ulonglong2* tab = (const ulonglong2*)(tb == 0 ? T0 : tb == 1 ? T1
                                                : tb == 2 ? T2 : T3);

    // moment accumulators (packed pairs covering d = 4*lane .. 4*lane+3)
    ull Txy = 0ull, Tzw = 0ull;     // P  = sum r
    ull Qxy = 0ull, Qzw = 0ull;     // Qn = -sum(prefix)

#define ROW_STEP(R_)                         \
    {                                        \
        Txy = add2(Txy, (R_).x);             \
        Tzw = add2(Tzw, (R_).y);             \
        Qxy = sub2(Qxy, Txy);                \
        Qzw = sub2(Qzw, Tzw);                \
    }

    const int start = (Sn * warp) >> 2;        // {0,12,25,37}
    const int end   = (Sn * (warp + 1)) >> 2;  // {12,25,37,50}
    int s = start;
    for (; s + 4 <= end; s += 4) {
        int w0 = idx[s], w1 = idx[s + 1], w2i = idx[s + 2], w3 = idx[s + 3];
        ulonglong2 r0 = tab[w0  * 32 + lane];
        ulonglong2 r1 = tab[w1  * 32 + lane];
        ulonglong2 r2 = tab[w2i * 32 + lane];
        ulonglong2 r3 = tab[w3  * 32 + lane];
        ROW_STEP(r0);
        ROW_STEP(r1);
        ROW_STEP(r2);
        ROW_STEP(r3);
    }
    for (; s < end; s++) {
        ulonglong2 r = tab[idx[s] * 32 + lane];
        ROW_STEP(r);
    }
#undef ROW_STEP

    // per-warp fixup: S1 = (end+1)*P + Qn   (global s' = start+k, k local)
    const float kcf = (float)(end + 1);
    const ull   kc2 = pack2(kcf, kcf);
    ull S1xy = fma2(kc2, Txy, Qxy);
    ull S1zw = fma2(kc2, Tzw, Qzw);

    // combine: emb = (1-c)*P + ((2c-1)/50)*S1
    const float c0 = (float)(4 * lane + 1) * (1.0f / Dn);
    const float c1 = (float)(4 * lane + 2) * (1.0f / Dn);
    const float c2 = (float)(4 * lane + 3) * (1.0f / Dn);
    const float c3 = (float)(4 * lane + 4) * (1.0f / Dn);
    const ull e1xy = pack2(1.0f - c0, 1.0f - c1);
    const ull e1zw = pack2(1.0f - c2, 1.0f - c3);
    const ull e2xy = pack2((2.0f * c0 - 1.0f) * (1.0f / Sn),
                           (2.0f * c1 - 1.0f) * (1.0f / Sn));
    const ull e2zw = pack2((2.0f * c2 - 1.0f) * (1.0f / Sn),
                           (2.0f * c3 - 1.0f) * (1.0f / Sn));
    ull rxy = fma2(e2xy, S1xy, mul2(e1xy, Txy));
    ull rzw = fma2(e2zw, S1zw, mul2(e1zw, Tzw));

    float2 fxy = unpack2(rxy), fzw = unpack2(rzw);
    part[warp][lane] = make_float4(fxy.x, fxy.y, fzw.x, fzw.y);
    __syncthreads();
    if (warp == 0) {
        float4 a0 = part[0][lane], a1 = part[1][lane];
        float4 a2 = part[2][lane], a3 = part[3][lane];
        float4 r;
        r.x = (a0.x + a1.x) + (a2.x + a3.x);
        r.y = (a0.y + a1.y) + (a2.y + a3.y);
        r.z = (a0.z + a1.z) + (a2.z + a3.z);
        r.w = (a0.w + a1.w) + (a2.w + a3.w);
        ((float4*)g_emb[tb][bm])[lane] = r;
    }
}

// ---------------------------------------------------------------------------
// Kernel 2: query embed + 3 hops (exact R4 version, proven).
// ---------------------------------------------------------------------------
__global__ void __launch_bounds__(1024) hops_kernel(
    const int* __restrict__ question, const float* __restrict__ Bemb,
    const float* __restrict__ TA, const float* __restrict__ TC)
{
    __shared__ float u_sh[Dn];
    __shared__ float sc[Mn];
    __shared__ float scp[Mn][33];        // padded: conflict-free transpose
    __shared__ float partial[8][Dn];
    __shared__ float red[32];
    __shared__ float s_max, s_sum;
    __shared__ int   qidx[Qn];
    __shared__ float qa[Qn], qb[Qn];

    const int b    = blockIdx.x;
    const int t    = threadIdx.x;
    const int warp = t >> 5;
    const int lane = t & 31;

    // ---- query embedding u^1 ----
    if (t < Qn) {
        int w = question[b * Qn + t];
        qidx[t] = w;
        float j = (float)(t + 1);
        qa[t] = 1.0f - j * (1.0f / Qn);
        qb[t] = 2.0f * j * (1.0f / Qn) - 1.0f;
    }
    __syncthreads();
    if (t < Dn) {
        const float cd = (float)(t + 1) * (1.0f / Dn);
        float acc = 0.f;
#pragma unroll
        for (int q = 0; q < Qn; q++) {
            float wgt = fmaf(qb[q], cd, qa[q]);
            acc = fmaf(wgt, Bemb[qidx[q] * Dn + t], acc);
        }
        u_sh[t] = acc;
    }
    __syncthreads();

    for (int k = 0; k < HOPSn; k++) {
        const float4* embA = (const float4*)g_emb[k];
        const float*  embC = (const float*)g_emb[k + 1];

        // ---- per-lane score partials (no shfl): warp covers m stride 32 ----
        float4 uu = ((const float4*)u_sh)[lane];
#pragma unroll 2
        for (int m = warp; m < Mn; m += 32) {
            float4 e  = embA[(b * Mn + m) * (Dn / 4) + lane];
            float4 ta = ((const float4*)TA)[m * (Dn / 4) + lane];
            float p = (e.x + ta.x) * uu.x + (e.y + ta.y) * uu.y
                    + (e.z + ta.z) * uu.z + (e.w + ta.w) * uu.w;
            scp[m][lane] = p;
        }
        __syncthreads();

        // ---- reduce 32 partials per m (4-way split accumulators) ----
        float lm = -3e38f;
        if (t < Mn) {
            float p0 = 0.f, p1 = 0.f, p2 = 0.f, p3 = 0.f;
#pragma unroll
            for (int i = 0; i < 32; i += 4) {
                p0 += scp[t][i];
                p1 += scp[t][i + 1];
                p2 += scp[t][i + 2];
                p3 += scp[t][i + 3];
            }
            float p = (p0 + p1) + (p2 + p3);
            p = g_nonpad[b * Mn + t] ? p : NEG_INF;
            sc[t] = p;
            lm = p;
        }
        // ---- softmax max ----
#pragma unroll
        for (int off = 16; off; off >>= 1)
            lm = fmaxf(lm, __shfl_down_sync(0xffffffffu, lm, off));
        if (lane == 0) red[warp] = lm;
        __syncthreads();
        if (warp == 0) {
            float v = red[lane];
#pragma unroll
            for (int off = 16; off; off >>= 1)
                v = fmaxf(v, __shfl_down_sync(0xffffffffu, v, off));
            if (lane == 0) s_max = v;
        }
        __syncthreads();
        // ---- exp + sum ----
        float e = 0.f;
        if (t < Mn) {
            e = __expf(sc[t] - s_max);
            sc[t] = e;
        }
#pragma unroll
        for (int off = 16; off; off >>= 1)
            e += __shfl_down_sync(0xffffffffu, e, off);
        if (lane == 0) red[warp] = e;
        __syncthreads();
        if (warp == 0) {
            float v = red[lane];
#pragma unroll
            for (int off = 16; off; off >>= 1)
                v += __shfl_down_sync(0xffffffffu, v, off);
            if (lane == 0) s_sum = v;
        }
        __syncthreads();
        const float inv = 1.0f / s_sum;

        // ---- o[d] = sum_m p[m]*(c_k[m,d]+TC[m,d]) : 8 groups x 128 ----
        const int g = t >> 7;     // group 0..7
        const int d = t & 127;    // dim
        float o = 0.f;
#pragma unroll
        for (int mi = 0; mi < Mn / 8; mi++) {
            int m = g + mi * 8;
            float c = embC[(b * Mn + m) * Dn + d] + TC[m * Dn + d];
            o = fmaf(sc[m], c, o);
        }
        partial[g][d] = o;
        __syncthreads();
        if (t < Dn) {
            float s2 = 0.f;
#pragma unroll
            for (int g2 = 0; g2 < 8; g2++) s2 += partial[g2][t];
            u_sh[t] += s2 * inv;
        }
        __syncthreads();
    }
    if (t < Dn) g_u[b][t] = u_sh[t];
}

// ---------------------------------------------------------------------------
// Kernel 3: logits = u @ W^T + bias, FFMA2 version.
//  grid.y = batch half (32 b's per block, packed even/odd-d accumulators).
//  Per (d4, 32b): 32 broadcast LDS.128 + 64 FFMA2 (FMA work halves vs R4).
// ---------------------------------------------------------------------------
__global__ void __launch_bounds__(128) logits_kernel(
    const float* __restrict__ W, const float* __restrict__ bias,
    float* __restrict__ out)
{
    __shared__ ulonglong2 u_sh[32 * 32];   // [b][d4], 16 KB
    const int t  = threadIdx.x;
    const int bh = blockIdx.y;             // batch half: 0 or 1
    const float4* gu4 = ((const float4*)g_u) + bh * (32 * (Dn / 4));
#pragma unroll
    for (int i = 0; i < 8; i++)
        ((float4*)u_sh)[t + i * 128] = gu4[t + i * 128];
    __syncthreads();

    const int v = blockIdx.x * 128 + t;
    if (v >= Vn) return;

    const ulonglong2* Wv = (const ulonglong2*)(W + (size_t)v * Dn);
    ull acc[32];
#pragma unroll
    for (int b = 0; b < 32; b++) acc[b] = 0ull;

#pragma unroll 1
    for (int d4 = 0; d4 < Dn / 4; d4++) {
        ulonglong2 w2 = Wv[d4];            // (w0,w1) (w2,w3)
#pragma unroll
        for (int b = 0; b < 32; b++) {
            ulonglong2 u2 = u_sh[b * 32 + d4];   // broadcast across warp
            acc[b] = fma2(w2.x, u2.x, acc[b]);
            acc[b] = fma2(w2.y, u2.y, acc[b]);
        }
    }
    const float bv = bias[v];
#pragma unroll
    for (int b = 0; b < 32; b++) {
        float2 p = unpack2(acc[b]);
        out[(size_t)(bh * 32 + b) * Vn + v] = (p.x + p.y) + bv;
    }
}

// ---------------------------------------------------------------------------
extern "C" void kernel_launch(void* const* d_in, const int* in_sizes, int n_in,
                              void* d_out, int out_size)
{
    const int*   story    = (const int*)d_in[0];
    const int*   question = (const int*)d_in[1];
    const float* A0       = (const float*)d_in[2];
    const float* C0       = (const float*)d_in[3];
    const float* C1       = (const float*)d_in[4];
    const float* C2       = (const float*)d_in[5];
    const float* Bemb     = (const float*)d_in[6];
    const float* TA       = (const float*)d_in[7];
    const float* TC       = (const float*)d_in[8];
    const float* W        = (const float*)d_in[9];
    const float* bias     = (const float*)d_in[10];
    float* out = (float*)d_out;

    embed_story_kernel<<<dim3(Bn * Mn, 4), 128>>>(story, A0, C0, C1, C2);
    hops_kernel<<<Bn, 1024>>>(question, Bemb, TA, TC);
    logits_kernel<<<dim3((Vn + 127) / 128, 2), 128>>>(W, bias, out);
}